// round 8
// baseline (speedup 1.0000x reference)
#include <cuda_runtime.h>
#include <cuda_fp16.h>
#include <cstdint>

#define B_  8
#define S_  2048
#define DV_ 768
#define DA_ 512
#define K_  512
#define M_  (B_*S_)   // 16384

#define TILE_M 128
#define TILE_N 128
#define NST 5
#define PRE 4
#define SMB_OFF 16384                          // A tile bytes (128 rows x 128B)
#define ST_BYTES 32768                         // A + B
#define DYN_SMEM (NST*ST_BYTES + 256)
#define PEFF_NST 4
#define PEFF_SMEM (PEFF_NST*ST_BYTES + 256)
#define CROSS_INV_SCALE 0.03125f               // P_eff stored x32

// ---- scratch (__device__ globals; alloc-guard-safe) ----
__device__ __align__(1024) __half  g_fvh[M_*DV_];   // feat_vision fp16
__device__ __align__(1024) __half  g_fah[M_*DA_];   // feat_audio fp16
__device__ __align__(1024) uint8_t g_sv8[M_*DV_];   // smoothed vision e4m3
__device__ __align__(1024) uint8_t g_sa8[M_*DA_];   // smoothed audio e4m3
__device__ __align__(1024) __half  g_pvh[K_*DV_];   // proto_vision fp16
__device__ __align__(1024) __half  g_pah[K_*DA_];   // proto_audio fp16
__device__ __align__(1024) uint8_t g_pev8[K_*DA_];  // (proto_v @ Wav) * 32, e4m3
__device__ __align__(1024) uint8_t g_pea8[K_*DV_];  // (proto_a @ Wva) * 32, e4m3
__device__ __align__(1024) __half  g_wtav[DA_*DV_]; // Wav^T (DA, DV) fp16
__device__ __align__(1024) __half  g_wtva[DV_*DA_]; // Wva^T (DV, DA) fp16
__device__ double g_acc;

__global__ void final_k(float* __restrict__ out) { out[0] = (float)(-g_acc); }

// ---------------- low-level helpers ----------------
__device__ __forceinline__ uint32_t smem_u32(const void* p) {
    uint32_t a;
    asm("{ .reg .u64 t; cvta.to.shared.u64 t, %1; cvt.u32.u64 %0, t; }" : "=r"(a) : "l"(p));
    return a;
}
__device__ __forceinline__ uint32_t swz(uint32_t o) { return o ^ ((o >> 3) & 0x70u); }

__device__ __forceinline__ void cpa16(uint32_t d, const void* s) {
    asm volatile("cp.async.cg.shared.global [%0], [%1], 16;" :: "r"(d), "l"(s));
}
#define CP_COMMIT() asm volatile("cp.async.commit_group;" ::: "memory")
#define CP_WAIT(n)  asm volatile("cp.async.wait_group %0;" :: "n"(n) : "memory")

__device__ __forceinline__ void ldsm4(uint32_t* r, uint32_t addr) {
    asm volatile("ldmatrix.sync.aligned.m8n8.x4.shared.b16 {%0,%1,%2,%3}, [%4];"
        : "=r"(r[0]), "=r"(r[1]), "=r"(r[2]), "=r"(r[3]) : "r"(addr));
}
__device__ __forceinline__ void mma_f16(float* d, const uint32_t* a, const uint32_t* b) {
    asm volatile("mma.sync.aligned.m16n8k16.row.col.f32.f16.f16.f32 "
        "{%0,%1,%2,%3}, {%4,%5,%6,%7}, {%8,%9}, {%0,%1,%2,%3};"
        : "+f"(d[0]), "+f"(d[1]), "+f"(d[2]), "+f"(d[3])
        : "r"(a[0]), "r"(a[1]), "r"(a[2]), "r"(a[3]), "r"(b[0]), "r"(b[1]));
}
__device__ __forceinline__ void mma_e4m3(float* d, const uint32_t* a, const uint32_t* b) {
    asm volatile("mma.sync.aligned.m16n8k32.row.col.f32.e4m3.e4m3.f32 "
        "{%0,%1,%2,%3}, {%4,%5,%6,%7}, {%8,%9}, {%0,%1,%2,%3};"
        : "+f"(d[0]), "+f"(d[1]), "+f"(d[2]), "+f"(d[3])
        : "r"(a[0]), "r"(a[1]), "r"(a[2]), "r"(a[3]), "r"(b[0]), "r"(b[1]));
}

// pack (lo, hi) floats -> 2x e4m3 bytes (lo in low byte)
__device__ __forceinline__ uint16_t f2e4m3x2(float lo, float hi) {
    uint16_t r;
    asm("cvt.rn.satfinite.e4m3x2.f32 %0, %1, %2;" : "=h"(r) : "f"(hi), "f"(lo));
    return r;
}

// ---------------- prologue kernels ----------------
__device__ __forceinline__ void cvt4(float4 v, __half* __restrict__ H, size_t idx4) {
    __half2* Hp = reinterpret_cast<__half2*>(H + idx4 * 4);
    Hp[0] = __floats2half2_rn(v.x, v.y);
    Hp[1] = __floats2half2_rn(v.z, v.w);
}
__device__ __forceinline__ void cvt4_fp8(float4 v, uint8_t* __restrict__ H, size_t idx4) {
    uint32_t w = (uint32_t)f2e4m3x2(v.x, v.y) | ((uint32_t)f2e4m3x2(v.z, v.w) << 16);
    reinterpret_cast<uint32_t*>(H)[idx4] = w;
}

__device__ __forceinline__ void prep_one(const float4* __restrict__ f,
                                         __half* __restrict__ fh, uint8_t* __restrict__ s8,
                                         int D4, int idx) {
    int t = (idx / D4) % S_;
    float4 c = f[idx];
    float4 sm = c;
    float cnt = 1.f;
    if (t > 0)      { float4 p = f[idx - D4]; sm.x += p.x; sm.y += p.y; sm.z += p.z; sm.w += p.w; cnt += 1.f; }
    if (t < S_ - 1) { float4 n = f[idx + D4]; sm.x += n.x; sm.y += n.y; sm.z += n.z; sm.w += n.w; cnt += 1.f; }
    float inv = 1.f / cnt;
    sm.x *= inv; sm.y *= inv; sm.z *= inv; sm.w *= inv;
    cvt4(c, fh, idx);
    cvt4_fp8(sm, s8, idx);
}

// both modalities: fp16 raw + window-3 smooth -> e4m3, one launch
__global__ void prep2_k(const float4* __restrict__ fv, __half* __restrict__ fvh,
                        uint8_t* __restrict__ sv8,
                        const float4* __restrict__ fa, __half* __restrict__ fah,
                        uint8_t* __restrict__ sa8) {
    const int totv = M_ * (DV_ / 4);
    const int tota = M_ * (DA_ / 4);
    int idx = blockIdx.x * blockDim.x + threadIdx.x;
    if (idx < totv)               prep_one(fv, fvh, sv8, DV_ / 4, idx);
    else if (idx < totv + tota)   prep_one(fa, fah, sa8, DA_ / 4, idx - totv);
}

// misc: zero acc + proto fp16 cvt + both W transposes, one launch
#define CVT_BLKS 640
__global__ void misc_k(const float4* __restrict__ pv, __half* __restrict__ pvh,
                       const float4* __restrict__ pa, __half* __restrict__ pah,
                       const float* __restrict__ Wav, __half* __restrict__ wtav,
                       const float* __restrict__ Wva, __half* __restrict__ wtva) {
    __shared__ float t[32][33];
    int bid = blockIdx.x, tid = threadIdx.x;
    if (bid == 0 && tid == 0) g_acc = 0.0;
    const int n4v = K_ * DV_ / 4, n4a = K_ * DA_ / 4;
    if (bid < CVT_BLKS) {
        int idx = bid * 256 + tid;
        if (idx < n4v)             cvt4(pv[idx], pvh, idx);
        else if (idx < n4v + n4a)  cvt4(pa[idx - n4v], pah, idx - n4v);
    } else {
        int b = bid - CVT_BLKS;
        const float* W; __half* Wt; int R, C, bx, by;
        if (b < 384) { W = Wav; Wt = wtav; R = DV_; C = DA_; bx = b % 24; by = b / 24; }
        else { b -= 384; W = Wva; Wt = wtva; R = DA_; C = DV_; bx = b % 16; by = b / 16; }
        int tx = tid & 31, ty = tid >> 5;
        int d0 = bx * 32, n0 = by * 32;
#pragma unroll
        for (int j = 0; j < 4; j++)
            t[ty + 8 * j][tx] = W[(size_t)(d0 + ty + 8 * j) * C + n0 + tx];
        __syncthreads();
#pragma unroll
        for (int j = 0; j < 4; j++)
            Wt[(size_t)(n0 + ty + 8 * j) * R + d0 + tx] = __float2half_rn(t[tx][ty + 8 * j]);
    }
}

// ---------------- shared GEMM building blocks ----------------
// fp16 chunk: 64 K-elems, rows of 128 bytes
__device__ __forceinline__ void load_chunk16(uint32_t st, const __half* Ap, const __half* Bp,
                                             int D, int rowBase, int colBase, int c, int tid) {
#pragma unroll
    for (int i = 0; i < 4; i++) {
        int e = tid + i * 256;
        int r = e >> 3, cg = e & 7;
        cpa16(st + swz((uint32_t)(r * 128 + cg * 16)),
              Ap + (size_t)(rowBase + r) * D + (c << 6) + cg * 8);
    }
    uint32_t sB = st + SMB_OFF;
#pragma unroll
    for (int i = 0; i < 4; i++) {
        int e = tid + i * 256;
        int r = e >> 3, cg = e & 7;
        cpa16(sB + swz((uint32_t)(r * 128 + cg * 16)),
              Bp + (size_t)(colBase + r) * D + (c << 6) + cg * 8);
    }
}
// fp8 chunk: 128 K-elems, rows of 128 bytes
__device__ __forceinline__ void load_chunk8(uint32_t st, const uint8_t* Ap, const uint8_t* Bp,
                                            int D, int rowBase, int colBase, int c, int tid) {
#pragma unroll
    for (int i = 0; i < 4; i++) {
        int e = tid + i * 256;
        int r = e >> 3, cg = e & 7;
        cpa16(st + swz((uint32_t)(r * 128 + cg * 16)),
              Ap + (size_t)(rowBase + r) * D + (c << 7) + cg * 16);
    }
    uint32_t sB = st + SMB_OFF;
#pragma unroll
    for (int i = 0; i < 4; i++) {
        int e = tid + i * 256;
        int r = e >> 3, cg = e & 7;
        cpa16(sB + swz((uint32_t)(r * 128 + cg * 16)),
              Bp + (size_t)(colBase + r) * D + (c << 7) + cg * 16);
    }
}

// byte-layout of e4m3 m16n8k32 fragments == f16 m16n8k16 fragments, so the
// ldmatrix addressing is shared; only the mma opcode differs.
template<bool F8>
__device__ __forceinline__ void compute_chunk(uint32_t sA, uint32_t sB,
                                              int aRow0, int aKb, int bRow0, int bKb,
                                              float (&acc)[2][8][4]) {
#pragma unroll
    for (int ks = 0; ks < 4; ks++) {
        uint32_t a[2][4], b[8][2];
#pragma unroll
        for (int im = 0; im < 2; im++) {
            uint32_t byte = (uint32_t)((aRow0 + im * 16) * 128 + ks * 32 + aKb);
            ldsm4(a[im], sA + swz(byte));
        }
#pragma unroll
        for (int g = 0; g < 4; g++) {
            uint32_t byte = (uint32_t)((bRow0 + g * 16) * 128 + ks * 32 + bKb);
            uint32_t r[4];
            ldsm4(r, sB + swz(byte));
            b[2 * g][0] = r[0]; b[2 * g][1] = r[1];
            b[2 * g + 1][0] = r[2]; b[2 * g + 1][1] = r[3];
        }
#pragma unroll
        for (int im = 0; im < 2; im++)
#pragma unroll
            for (int jn = 0; jn < 8; jn++) {
                if (F8) mma_e4m3(acc[im][jn], a[im], b[jn]);
                else    mma_f16 (acc[im][jn], a[im], b[jn]);
            }
    }
}

// ---------------- P_eff GEMM: O = A(512, D) @ Bt(N, D)^T, e4m3*32 out ----------------
__global__ __launch_bounds__(256, 1) void peff_mma_k(
    const __half* __restrict__ Av, const __half* __restrict__ Btv,
    uint8_t* __restrict__ Ov, int Dv, int Nv,
    const __half* __restrict__ Aa, const __half* __restrict__ Bta,
    uint8_t* __restrict__ Oa, int Da, int Na) {
    extern __shared__ char dsm[];

    const __half* A  = blockIdx.z ? Aa  : Av;
    const __half* Bt = blockIdx.z ? Bta : Btv;
    uint8_t* O = blockIdx.z ? Oa : Ov;
    const int D = blockIdx.z ? Da : Dv;
    const int N = blockIdx.z ? Na : Nv;
    if ((int)blockIdx.x * TILE_N >= N) return;

    const int tid  = threadIdx.x;
    const int wid  = tid >> 5;
    const int lane = tid & 31;
    const int wm = wid & 3;
    const int wn = wid >> 2;
    const int rowBase = blockIdx.y * TILE_M;
    const int colBase = blockIdx.x * TILE_N;

    uint32_t smem0 = (smem_u32(dsm) + 127u) & ~127u;

    const int aRow0 = wm * 32 + (lane & 15);
    const int aKb   = (lane >> 4) * 16;
    const int bRow0 = wn * 64 + (lane & 7) + ((lane >> 4) << 3);
    const int bKb   = ((lane >> 3) & 1) * 16;

    float acc[2][8][4];
#pragma unroll
    for (int im = 0; im < 2; im++)
#pragma unroll
        for (int jn = 0; jn < 8; jn++)
#pragma unroll
            for (int e = 0; e < 4; e++) acc[im][jn][e] = 0.f;

    const int n = D >> 6;
    for (int i = 0; i < 3; i++) {
        load_chunk16(smem0 + (uint32_t)(i & 3) * ST_BYTES, A, Bt, D, rowBase, colBase, i, tid);
        CP_COMMIT();
    }
    for (int i = 0; i < n; i++) {
        int w = n - 1 - i;
        if (w >= 2)      { CP_WAIT(2); }
        else if (w == 1) { CP_WAIT(1); }
        else             { CP_WAIT(0); }
        __syncthreads();
        int j = i + 3;
        if (j < n) {
            load_chunk16(smem0 + (uint32_t)(j & 3) * ST_BYTES, A, Bt, D, rowBase, colBase, j, tid);
            CP_COMMIT();
        }
        uint32_t sA = smem0 + (uint32_t)(i & 3) * ST_BYTES;
        compute_chunk<false>(sA, sA + SMB_OFF, aRow0, aKb, bRow0, bKb, acc);
    }

    // store e4m3 scaled x32 (standard m16n8 C fragment positions)
    const int r0 = rowBase + wm * 32 + (lane >> 2);
    const int c0 = colBase + wn * 64 + (lane & 3) * 2;
#pragma unroll
    for (int im = 0; im < 2; im++)
#pragma unroll
        for (int jn = 0; jn < 8; jn++) {
            int r = r0 + im * 16;
            int c = c0 + jn * 8;
            *reinterpret_cast<uint16_t*>(O + (size_t)r * N + c) =
                f2e4m3x2(acc[im][jn][0] * 32.f, acc[im][jn][1] * 32.f);
            *reinterpret_cast<uint16_t*>(O + (size_t)(r + 8) * N + c) =
                f2e4m3x2(acc[im][jn][2] * 32.f, acc[im][jn][3] * 32.f);
        }
}

// ---------------- fused dual-GEMM (fp16 intra + fp8 cross) + energy ----------------
struct ModParams {
    const __half* A1; const __half* B1; int D1;     // intra: feat . proto (fp16)
    const uint8_t* A2; const uint8_t* B2; int D2;   // cross: smooth . P_eff (e4m3)
};

__global__ __launch_bounds__(256, 1) void fused_mma_k(ModParams Pv, ModParams Pa) {
    extern __shared__ char dsm[];
    __shared__ float s_wsum[8];

    const ModParams P = blockIdx.z ? Pa : Pv;

    const int tid  = threadIdx.x;
    const int wid  = tid >> 5;
    const int lane = tid & 31;
    const int wm = wid & 3;
    const int wn = wid >> 2;
    const int rowBase = blockIdx.y * TILE_M;
    const int colBase = blockIdx.x * TILE_N;

    uint32_t smem0 = (smem_u32(dsm) + 127u) & ~127u;

    const int aRow0 = wm * 32 + (lane & 15);
    const int aKb   = (lane >> 4) * 16;
    const int bRow0 = wn * 64 + (lane & 7) + ((lane >> 4) << 3);
    const int bKb   = ((lane >> 3) & 1) * 16;

    float acc1[2][8][4], acc2[2][8][4];
#pragma unroll
    for (int im = 0; im < 2; im++)
#pragma unroll
        for (int jn = 0; jn < 8; jn++)
#pragma unroll
            for (int e = 0; e < 4; e++) { acc1[im][jn][e] = 0.f; acc2[im][jn][e] = 0.f; }

    const int C1 = P.D1 >> 6;    // fp16 intra chunks (64 elems)
    const int C2 = P.D2 >> 7;    // fp8 cross chunks (128 elems)
    const int n  = C1 + C2;      // vision 16, audio 14

    for (int i = 0; i < PRE; i++) {
        uint32_t st = smem0 + (uint32_t)(i % NST) * ST_BYTES;
        if (i < C1) load_chunk16(st, P.A1, P.B1, P.D1, rowBase, colBase, i, tid);
        else        load_chunk8 (st, P.A2, P.B2, P.D2, rowBase, colBase, i - C1, tid);
        CP_COMMIT();
    }

    for (int i = 0; i < n; i++) {
        int w = n - 1 - i;
        if (w >= 3)      { CP_WAIT(3); }
        else if (w == 2) { CP_WAIT(2); }
        else if (w == 1) { CP_WAIT(1); }
        else             { CP_WAIT(0); }
        __syncthreads();

        int j = i + PRE;
        if (j < n) {
            uint32_t st = smem0 + (uint32_t)(j % NST) * ST_BYTES;
            if (j < C1) load_chunk16(st, P.A1, P.B1, P.D1, rowBase, colBase, j, tid);
            else        load_chunk8 (st, P.A2, P.B2, P.D2, rowBase, colBase, j - C1, tid);
            CP_COMMIT();
        }

        uint32_t sA = smem0 + (uint32_t)(i % NST) * ST_BYTES;
        if (i < C1) compute_chunk<false>(sA, sA + SMB_OFF, aRow0, aKb, bRow0, bKb, acc1);
        else        compute_chunk<true> (sA, sA + SMB_OFF, aRow0, aKb, bRow0, bKb, acc2);
    }

    // epilogue: softplus(saliency * intra); cross carries 1/32 scale
    float local = 0.f;
#pragma unroll
    for (int im = 0; im < 2; im++)
#pragma unroll
        for (int jn = 0; jn < 8; jn++)
#pragma unroll
            for (int e = 0; e < 4; e++) {
                float x  = acc1[im][jn][e];
                float cr = acc2[im][jn][e] * CROSS_INV_SCALE;
                float sal = 0.3f * cr * cr + 0.7f * x * x;
                float z = sal * x;
                local += fmaxf(z, 0.f) + __logf(1.f + __expf(-fabsf(z)));
            }

#pragma unroll
    for (int off = 16; off; off >>= 1)
        local += __shfl_xor_sync(0xffffffffu, local, off);
    if (lane == 0) s_wsum[wid] = local;
    __syncthreads();
    if (tid == 0) {
        double v = 0.0;
#pragma unroll
        for (int w = 0; w < 8; w++) v += (double)s_wsum[w];
        atomicAdd(&g_acc, v);
    }
}

// ---------------------------------------------------------------------------
extern "C" void kernel_launch(void* const* d_in, const int* in_sizes, int n_in,
                              void* d_out, int out_size) {
    const float* fv  = (const float*)d_in[0];
    const float* fa  = (const float*)d_in[1];
    const float* pv  = (const float*)d_in[2];
    const float* pa  = (const float*)d_in[3];
    const float* Wav = (const float*)d_in[4];
    const float* Wva = (const float*)d_in[5];
    float* out = (float*)d_out;

    __half *fvh, *fah, *pvh, *pah, *wtav, *wtva;
    uint8_t *sv8, *sa8, *pev8, *pea8;
    cudaGetSymbolAddress((void**)&fvh, g_fvh);
    cudaGetSymbolAddress((void**)&fah, g_fah);
    cudaGetSymbolAddress((void**)&sv8, g_sv8);
    cudaGetSymbolAddress((void**)&sa8, g_sa8);
    cudaGetSymbolAddress((void**)&pvh, g_pvh);
    cudaGetSymbolAddress((void**)&pah, g_pah);
    cudaGetSymbolAddress((void**)&pev8, g_pev8);
    cudaGetSymbolAddress((void**)&pea8, g_pea8);
    cudaGetSymbolAddress((void**)&wtav, g_wtav);
    cudaGetSymbolAddress((void**)&wtva, g_wtva);

    // 1) misc: zero + proto cvt + W transposes (1408 blocks)
    misc_k<<<CVT_BLKS + 768, 256>>>((const float4*)pv, pvh, (const float4*)pa, pah,
                                    Wav, wtav, Wva, wtva);
    // 2) features: fp16 raw + fp8 smoothed
    {
        int tot = M_ * (DV_ / 4) + M_ * (DA_ / 4);
        prep2_k<<<(tot + 255) / 256, 256>>>((const float4*)fv, fvh, sv8,
                                            (const float4*)fa, fah, sa8);
    }
    // 3) P_eff (both modalities, e4m3 x32 out)
    cudaFuncSetAttribute(peff_mma_k, cudaFuncAttributeMaxDynamicSharedMemorySize, PEFF_SMEM);
    {
        dim3 g(DV_ / TILE_N, K_ / TILE_M, 2);
        peff_mma_k<<<g, 256, PEFF_SMEM>>>(pvh, wtav, pev8, DV_, DA_,
                                          pah, wtva, pea8, DA_, DV_);
    }
    // 4) fused dual-GEMM + energy
    ModParams Pv { fvh, pvh, DV_, sa8, pev8, DA_ };   // vision energy
    ModParams Pa { fah, pah, DA_, sv8, pea8, DV_ };   // audio energy
    cudaFuncSetAttribute(fused_mma_k, cudaFuncAttributeMaxDynamicSharedMemorySize, DYN_SMEM);
    dim3 grid(K_ / TILE_N, M_ / TILE_M, 2);
    fused_mma_k<<<grid, 256, DYN_SMEM>>>(Pv, Pa);

    // 5) result
    final_k<<<1, 1>>>(out);
}